// round 5
// baseline (speedup 1.0000x reference)
#include <cuda_runtime.h>
#include <cuda_bf16.h>

// CRF NLL: B=512, S=1024, T=64.
// inputs: 0 emissions (B,S,T) f32, 1 tags (B,S) i32, 2 mask (B,S) i32,
//         3 start (T) f32, 4 end (T) f32, 5 transitions (T,T) f32
// output: scalar f32 = -(sum_b ll_b) / (sum_b L_b)
//
// Scaled linear-domain forward algorithm (R3 scheme), but TWO independent
// batches per warp share one instruction stream: each chain's exposed
// latency (smem exchange, accumulator tails) is hidden by the other
// chain's FFMA issue. E = exp(trans) lives once in registers, shared.

#define B_ 512
#define S_ 1024
#define T_ 64
#define FULLMASK 0xffffffffu

__device__ float g_ll[B_];
__device__ float g_len[B_];

typedef unsigned long long ull;

__device__ __forceinline__ ull ffma2(ull a, ull b, ull c) {
    ull d;
    asm("fma.rn.f32x2 %0, %1, %2, %3;" : "=l"(d) : "l"(a), "l"(b), "l"(c));
    return d;
}
__device__ __forceinline__ ull fadd2(ull a, ull b) {
    ull d;
    asm("add.rn.f32x2 %0, %1, %2;" : "=l"(d) : "l"(a), "l"(b));
    return d;
}
__device__ __forceinline__ ull pack2(float lo, float hi) {
    ull r;
    asm("mov.b64 %0, {%1, %2};" : "=l"(r) : "f"(lo), "f"(hi));
    return r;
}
__device__ __forceinline__ void unpack2(ull v, float& lo, float& hi) {
    asm("mov.b64 {%0, %1}, %2;" : "=f"(lo), "=f"(hi) : "l"(v));
}

// 64 threads = 2 warps per block; each warp owns 2 batches. grid = 128.
__global__ void __launch_bounds__(64) crf_main(
    const float* __restrict__ emis,
    const int* __restrict__ tags,
    const int* __restrict__ mask,
    const float* __restrict__ start,
    const float* __restrict__ endt,
    const float* __restrict__ trans)
{
    __shared__ __align__(16) float sh_w[2][2][2][T_];  // [warp][batch][buf][col]

    const int lane = threadIdx.x & 31;
    const int wid  = threadIdx.x >> 5;   // 0..1
    const int bA   = blockIdx.x * 4 + wid * 2;
    const int bB   = bA + 1;

    const int j0 = 2 * lane;
    const int j1 = j0 + 1;

    // ---- E columns j0/j1, i-paired for f32x2 (shared by both batches) ----
    ull Ej0[T_ / 2];
    ull Ej1[T_ / 2];
#pragma unroll
    for (int m = 0; m < T_ / 2; m++) {
        float2 ra = *(const float2*)&trans[(2 * m) * T_ + j0];
        float2 rb = *(const float2*)&trans[(2 * m + 1) * T_ + j0];
        Ej0[m] = pack2(__expf(ra.x), __expf(rb.x));
        Ej1[m] = pack2(__expf(ra.y), __expf(rb.y));
    }

    const int baseA = bA * S_;
    const int baseB = bB * S_;
    const float* emA = emis + (size_t)baseA * T_;
    const float* emB = emis + (size_t)baseB * T_;

    // ---- lengths ----
    int la = 0, lb = 0;
#pragma unroll 4
    for (int s = lane; s < S_; s += 32) {
        la += mask[baseA + s];
        lb += mask[baseB + s];
    }
#pragma unroll
    for (int o = 16; o > 0; o >>= 1) {
        la += __shfl_xor_sync(FULLMASK, la, o);
        lb += __shfl_xor_sync(FULLMASK, lb, o);
    }
    const int LA = la, LB = lb;
    const int Lmax = LA > LB ? LA : LB;

    // ---- numerators ----
    float numA = 0.0f, numB = 0.0f;
#pragma unroll 2
    for (int s = 1 + lane; s < S_; s += 32) {
        if (s < LA) {
            int tp = tags[baseA + s - 1];
            int tc = tags[baseA + s];
            numA += trans[tp * T_ + tc] + emA[s * T_ + tc];
        }
        if (s < LB) {
            int tp = tags[baseB + s - 1];
            int tc = tags[baseB + s];
            numB += trans[tp * T_ + tc] + emB[s * T_ + tc];
        }
    }
#pragma unroll
    for (int o = 16; o > 0; o >>= 1) {
        numA += __shfl_xor_sync(FULLMASK, numA, o);
        numB += __shfl_xor_sync(FULLMASK, numB, o);
    }
    if (lane == 0) {
        int a0 = tags[baseA], al = tags[baseA + LA - 1];
        int b0 = tags[baseB], bl = tags[baseB + LB - 1];
        numA += start[a0] + emA[a0] + endt[al];
        numB += start[b0] + emB[b0] + endt[bl];
    }

    // ---- recursion init (both batches) ----
    const float2* epA = (const float2*)emA;
    const float2* epB = (const float2*)emB;

    float2 e0A = epA[lane];
    float2 e0B = epB[lane];
    float wA0 = __expf(start[j0] + e0A.x);
    float wA1 = __expf(start[j1] + e0A.y);
    float wB0 = __expf(start[j0] + e0B.x);
    float wB1 = __expf(start[j1] + e0B.y);

    float2 pA1 = epA[1 * (T_ / 2) + lane];
    float2 pA2 = epA[2 * (T_ / 2) + lane];
    float2 pB1 = epB[1 * (T_ / 2) + lane];
    float2 pB2 = epB[2 * (T_ / 2) + lane];
    float FA0 = __expf(pA1.x), FA1 = __expf(pA1.y);
    float FB0 = __expf(pB1.x), FB1 = __expf(pB1.y);
    pA1 = pA2; pA2 = epA[3 * (T_ / 2) + lane];
    pB1 = pB2; pB2 = epB[3 * (T_ / 2) + lane];

    float rA, rB;
    int   kA, kB;
    {
        float wa = __shfl_sync(FULLMASK, wA0, 0);
        float wb = __shfl_sync(FULLMASK, wB0, 0);
        int ka = ((__float_as_int(wa) >> 23) & 0xff) - 127;
        int kb = ((__float_as_int(wb) >> 23) & 0xff) - 127;
        ka = max(-126, min(126, ka));
        kb = max(-126, min(126, kb));
        rA = __int_as_float((127 - ka) << 23); kA = ka;
        rB = __int_as_float((127 - kb) << 23); kB = kb;
    }
    float csA = 0.0f, csB = 0.0f;

    for (int s = 1; s < Lmax; s++) {
        const int pb = s & 1;
        *(float2*)&sh_w[wid][0][pb][j0] = make_float2(wA0, wA1);
        *(float2*)&sh_w[wid][1][pb][j0] = make_float2(wB0, wB1);
        __syncwarp();

        const bool actA = (s < LA);
        const bool actB = (s < LB);

        // off-chain: next emissions
        float FnA0 = __expf(pA1.x), FnA1 = __expf(pA1.y);
        float FnB0 = __expf(pB1.x), FnB1 = __expf(pB1.y);
        pA1 = pA2; pB1 = pB2;
        int sp = s + 4; if (sp > S_ - 1) sp = S_ - 1;
        pA2 = epA[sp * (T_ / 2) + lane];
        pB2 = epB[sp * (T_ / 2) + lane];

        // matvecs (ptxas interleaves the two independent chains)
        const ulonglong2* qA = (const ulonglong2*)sh_w[wid][0][pb];
        const ulonglong2* qB = (const ulonglong2*)sh_w[wid][1][pb];
        ull aA00 = 0ull, aA01 = 0ull, aA10 = 0ull, aA11 = 0ull;
        ull aB00 = 0ull, aB01 = 0ull, aB10 = 0ull, aB11 = 0ull;
#pragma unroll
        for (int m = 0; m < 16; m++) {
            ulonglong2 vA = qA[m];
            ulonglong2 vB = qB[m];
            aA00 = ffma2(vA.x, Ej0[2 * m],     aA00);
            aA01 = ffma2(vA.y, Ej0[2 * m + 1], aA01);
            aA10 = ffma2(vA.x, Ej1[2 * m],     aA10);
            aA11 = ffma2(vA.y, Ej1[2 * m + 1], aA11);
            aB00 = ffma2(vB.x, Ej0[2 * m],     aB00);
            aB01 = ffma2(vB.y, Ej0[2 * m + 1], aB01);
            aB10 = ffma2(vB.x, Ej1[2 * m],     aB10);
            aB11 = ffma2(vB.y, Ej1[2 * m + 1], aB11);
        }
        ull tA0 = fadd2(aA00, aA01), tA1 = fadd2(aA10, aA11);
        ull tB0 = fadd2(aB00, aB01), tB1 = fadd2(aB10, aB11);
        float xl, xh, yl, yh;

        unpack2(tA0, xl, xh); unpack2(tA1, yl, yh);
        float nA0 = (xl + xh) * (FA0 * rA);
        float nA1 = (yl + yh) * (FA1 * rA);
        unpack2(tB0, xl, xh); unpack2(tB1, yl, yh);
        float nB0 = (xl + xh) * (FB0 * rB);
        float nB1 = (yl + yh) * (FB1 * rB);

        // predicated commit (freeze past L)
        wA0 = actA ? nA0 : wA0;  wA1 = actA ? nA1 : wA1;
        wB0 = actB ? nB0 : wB0;  wB1 = actB ? nB1 : wB1;
        csA += actA ? (float)kA : 0.0f;
        csB += actB ? (float)kB : 0.0f;

        // resample rescale exponents from the just-committed w (stable)
        float wa = __shfl_sync(FULLMASK, wA0, 0);
        float wb = __shfl_sync(FULLMASK, wB0, 0);
        int ka = ((__float_as_int(wa) >> 23) & 0xff) - 127;
        int kb = ((__float_as_int(wb) >> 23) & 0xff) - 127;
        ka = max(-126, min(126, ka));
        kb = max(-126, min(126, kb));
        rA = __int_as_float((127 - ka) << 23); kA = ka;
        rB = __int_as_float((127 - kb) << 23); kB = kb;

        FA0 = FnA0; FA1 = FnA1;
        FB0 = FnB0; FB1 = FnB1;
    }

    // ---- denominators ----
    float eE0 = __expf(endt[j0]);
    float eE1 = __expf(endt[j1]);
    float eA = wA0 * eE0 + wA1 * eE1;
    float eB = wB0 * eE0 + wB1 * eE1;
#pragma unroll
    for (int o = 16; o > 0; o >>= 1) {
        eA += __shfl_xor_sync(FULLMASK, eA, o);
        eB += __shfl_xor_sync(FULLMASK, eB, o);
    }
    if (lane == 0) {
        float denA = (float)((double)csA * 0.6931471805599453) + __logf(eA);
        float denB = (float)((double)csB * 0.6931471805599453) + __logf(eB);
        g_ll[bA]  = numA - denA;
        g_ll[bB]  = numB - denB;
        g_len[bA] = (float)LA;
        g_len[bB] = (float)LB;
    }
}

__global__ void crf_finalize(float* __restrict__ out) {
    __shared__ float s_ll[16];
    __shared__ float s_ln[16];
    int t = threadIdx.x;  // 512 threads
    float ll = g_ll[t];
    float ln = g_len[t];
#pragma unroll
    for (int o = 16; o > 0; o >>= 1) {
        ll += __shfl_xor_sync(FULLMASK, ll, o);
        ln += __shfl_xor_sync(FULLMASK, ln, o);
    }
    int w = t >> 5;
    if ((t & 31) == 0) { s_ll[w] = ll; s_ln[w] = ln; }
    __syncthreads();
    if (t == 0) {
        float sll = 0.0f, sln = 0.0f;
#pragma unroll
        for (int i = 0; i < 16; i++) { sll += s_ll[i]; sln += s_ln[i]; }
        out[0] = -(sll / sln);
    }
}

extern "C" void kernel_launch(void* const* d_in, const int* in_sizes, int n_in,
                              void* d_out, int out_size) {
    const float* emis  = (const float*)d_in[0];
    const int*   tags  = (const int*)d_in[1];
    const int*   mask  = (const int*)d_in[2];
    const float* start = (const float*)d_in[3];
    const float* endt  = (const float*)d_in[4];
    const float* trans = (const float*)d_in[5];
    float* out = (float*)d_out;

    crf_main<<<B_ / 4, 64>>>(emis, tags, mask, start, endt, trans);
    crf_finalize<<<1, B_>>>(out);
}

// round 6
// speedup vs baseline: 1.9073x; 1.9073x over previous
#include <cuda_runtime.h>
#include <cuda_bf16.h>

// CRF NLL: B=512, S=1024, T=64.
// inputs: 0 emissions (B,S,T) f32, 1 tags (B,S) i32, 2 mask (B,S) i32,
//         3 start (T) f32, 4 end (T) f32, 5 transitions (T,T) f32
// output: scalar f32 = -(sum_b ll_b) / (sum_b L_b)
//
// R3 scheme (scaled linear-domain forward, 1 batch/warp, no exp/log on the
// chain) repacked as 8 warps/block x 64 blocks -> 2 warps per SMSP, so the
// warp scheduler interleaves two independent batch chains and hides each
// chain's exposed latency behind the other's FFMA issue.

#define B_ 512
#define S_ 1024
#define T_ 64
#define FULLMASK 0xffffffffu
#define WPB 8   // warps per block

__device__ float g_ll[B_];
__device__ float g_len[B_];

typedef unsigned long long ull;

__device__ __forceinline__ ull ffma2(ull a, ull b, ull c) {
    ull d;
    asm("fma.rn.f32x2 %0, %1, %2, %3;" : "=l"(d) : "l"(a), "l"(b), "l"(c));
    return d;
}
__device__ __forceinline__ ull fadd2(ull a, ull b) {
    ull d;
    asm("add.rn.f32x2 %0, %1, %2;" : "=l"(d) : "l"(a), "l"(b));
    return d;
}
__device__ __forceinline__ ull pack2(float lo, float hi) {
    ull r;
    asm("mov.b64 %0, {%1, %2};" : "=l"(r) : "f"(lo), "f"(hi));
    return r;
}
__device__ __forceinline__ void unpack2(ull v, float& lo, float& hi) {
    asm("mov.b64 {%0, %1}, %2;" : "=f"(lo), "=f"(hi) : "l"(v));
}

// 8 warps per block, one batch per warp. grid = 64.
__global__ void __launch_bounds__(32 * WPB) crf_main(
    const float* __restrict__ emis,
    const int* __restrict__ tags,
    const int* __restrict__ mask,
    const float* __restrict__ start,
    const float* __restrict__ endt,
    const float* __restrict__ trans)
{
    __shared__ __align__(16) float sh_w[WPB][2][T_];  // per-warp, double-buffered

    const int lane = threadIdx.x & 31;
    const int wid  = threadIdx.x >> 5;
    const int b    = blockIdx.x * WPB + wid;

    const int j0 = 2 * lane;
    const int j1 = j0 + 1;

    // ---- E = exp(trans), columns j0/j1, i-paired for f32x2 ----
    ull Ej0[T_ / 2];
    ull Ej1[T_ / 2];
#pragma unroll
    for (int m = 0; m < T_ / 2; m++) {
        float2 ra = *(const float2*)&trans[(2 * m) * T_ + j0];
        float2 rb = *(const float2*)&trans[(2 * m + 1) * T_ + j0];
        Ej0[m] = pack2(__expf(ra.x), __expf(rb.x));
        Ej1[m] = pack2(__expf(ra.y), __expf(rb.y));
    }

    const int base = b * S_;

    // ---- sequence length L (prefix mask) ----
    int len_part = 0;
#pragma unroll 4
    for (int s = lane; s < S_; s += 32) len_part += mask[base + s];
#pragma unroll
    for (int o = 16; o > 0; o >>= 1) len_part += __shfl_xor_sync(FULLMASK, len_part, o);
    const int L = len_part;

    // ---- numerator (gold-path score) ----
    float num = 0.0f;
    for (int s = 1 + lane; s < L; s += 32) {
        int tp = tags[base + s - 1];
        int tc = tags[base + s];
        num += trans[tp * T_ + tc] + emis[(size_t)b * S_ * T_ + s * T_ + tc];
    }
#pragma unroll
    for (int o = 16; o > 0; o >>= 1) num += __shfl_xor_sync(FULLMASK, num, o);
    {
        int tg0 = tags[base];
        int tgl = tags[base + L - 1];
        num += start[tg0] + emis[(size_t)b * S_ * T_ + tg0] + endt[tgl];
    }

    // ---- forward recursion (scaled linear domain) ----
    const float2* emp = (const float2*)(emis + (size_t)b * S_ * T_);
    float2 em0 = emp[lane];  // s = 0
    float w0 = __expf(start[j0] + em0.x);
    float w1 = __expf(start[j1] + em0.y);

    // emission prefetch: F = exp(em[s]); p1 = em[s+1], p2 = em[s+2]
    float2 p1 = emp[1 * (T_ / 2) + lane];
    float2 p2 = emp[2 * (T_ / 2) + lane];
    float F0 = __expf(p1.x);
    float F1 = __expf(p1.y);
    p1 = p2;
    p2 = emp[3 * (T_ / 2) + lane];

    // initial rescale from initial w (warp-uniform via lane 0)
    float r;
    int   kcur;
    {
        float w00 = __shfl_sync(FULLMASK, w0, 0);
        int k = ((__float_as_int(w00) >> 23) & 0xff) - 127;
        k = max(-126, min(126, k));
        r = __int_as_float((127 - k) << 23);
        kcur = k;
    }
    float csum = 0.0f;

    for (int s = 1; s < L; s++) {
        const int pb = s & 1;
        *(float2*)&sh_w[wid][pb][j0] = make_float2(w0, w1);
        __syncwarp();

        // off-chain: exp(em[s+1]) for next step, advance prefetch
        float Fn0 = __expf(p1.x);
        float Fn1 = __expf(p1.y);
        p1 = p2;
        int sp = s + 3; if (sp >= S_) sp = S_ - 1;
        p2 = emp[sp * (T_ / 2) + lane];

        // matvec: v[j] = sum_i w[i] * E[i][j]
        const ulonglong2* q = (const ulonglong2*)sh_w[wid][pb];
        ull a00 = 0ull, a01 = 0ull, a02 = 0ull, a03 = 0ull;
        ull a10 = 0ull, a11 = 0ull, a12 = 0ull, a13 = 0ull;
#pragma unroll
        for (int m = 0; m < 8; m++) {
            ulonglong2 va = q[2 * m];      // w[8m..8m+3]
            ulonglong2 vb = q[2 * m + 1];  // w[8m+4..8m+7]
            a00 = ffma2(va.x, Ej0[4 * m + 0], a00);
            a01 = ffma2(va.y, Ej0[4 * m + 1], a01);
            a02 = ffma2(vb.x, Ej0[4 * m + 2], a02);
            a03 = ffma2(vb.y, Ej0[4 * m + 3], a03);
            a10 = ffma2(va.x, Ej1[4 * m + 0], a10);
            a11 = ffma2(va.y, Ej1[4 * m + 1], a11);
            a12 = ffma2(vb.x, Ej1[4 * m + 2], a12);
            a13 = ffma2(vb.y, Ej1[4 * m + 3], a13);
        }
        ull t0 = fadd2(fadd2(a00, a01), fadd2(a02, a03));
        ull t1 = fadd2(fadd2(a10, a11), fadd2(a12, a13));
        float s0l, s0h, s1l, s1h;
        unpack2(t0, s0l, s0h);
        unpack2(t1, s1l, s1h);

        // apply emission + pending rescale (r = 2^-kcur from previous w)
        w0 = (s0l + s0h) * (F0 * r);
        w1 = (s1l + s1h) * (F1 * r);
        csum += (float)kcur;

        // sample k from the w just computed (stable: x' = frac(x) + g);
        // shfl sits in the latency shadow of the next matvec.
        float w00 = __shfl_sync(FULLMASK, w0, 0);
        int k = ((__float_as_int(w00) >> 23) & 0xff) - 127;
        k = max(-126, min(126, k));
        r = __int_as_float((127 - k) << 23);
        kcur = k;

        F0 = Fn0;
        F1 = Fn1;
    }

    // ---- denominator = csum*ln2 + log( sum_j w[j]*exp(end[j]) ) ----
    float e = w0 * __expf(endt[j0]) + w1 * __expf(endt[j1]);
#pragma unroll
    for (int o = 16; o > 0; o >>= 1) e += __shfl_xor_sync(FULLMASK, e, o);
    float den = (float)((double)csum * 0.6931471805599453) + __logf(e);

    if (lane == 0) {
        g_ll[b]  = num - den;
        g_len[b] = (float)L;
    }
}

__global__ void crf_finalize(float* __restrict__ out) {
    __shared__ float s_ll[16];
    __shared__ float s_ln[16];
    int t = threadIdx.x;  // 512 threads
    float ll = g_ll[t];
    float ln = g_len[t];
#pragma unroll
    for (int o = 16; o > 0; o >>= 1) {
        ll += __shfl_xor_sync(FULLMASK, ll, o);
        ln += __shfl_xor_sync(FULLMASK, ln, o);
    }
    int w = t >> 5;
    if ((t & 31) == 0) { s_ll[w] = ll; s_ln[w] = ln; }
    __syncthreads();
    if (t == 0) {
        float sll = 0.0f, sln = 0.0f;
#pragma unroll
        for (int i = 0; i < 16; i++) { sll += s_ll[i]; sln += s_ln[i]; }
        out[0] = -(sll / sln);
    }
}

extern "C" void kernel_launch(void* const* d_in, const int* in_sizes, int n_in,
                              void* d_out, int out_size) {
    const float* emis  = (const float*)d_in[0];
    const int*   tags  = (const int*)d_in[1];
    const int*   mask  = (const int*)d_in[2];
    const float* start = (const float*)d_in[3];
    const float* endt  = (const float*)d_in[4];
    const float* trans = (const float*)d_in[5];
    float* out = (float*)d_out;

    crf_main<<<B_ / WPB, 32 * WPB>>>(emis, tags, mask, start, endt, trans);
    crf_finalize<<<1, B_>>>(out);
}

// round 7
// speedup vs baseline: 2.9578x; 1.5508x over previous
#include <cuda_runtime.h>
#include <cuda_bf16.h>

// CRF NLL: B=512, S=1024, T=64.
// inputs: 0 emissions (B,S,T) f32, 1 tags (B,S) i32, 2 mask (B,S) i32,
//         3 start (T) f32, 4 end (T) f32, 5 transitions (T,T) f32
// output: scalar f32 = -(sum_b ll_b) / (sum_b L_b)
//
// Forward-backward split: Z = sum_i alpha_mid[i] * beta_mid[i].
// Each batch = TWO independent scaled linear-domain chains of length ~L/2
// (forward alpha, backward beta), one warp each, joined once at the end.
// 1024 warps -> 2 per SMSP on 128 SMs; the scheduler hides each chain's
// exposed latency behind the other's FFMA issue. No exp/log on any chain.

#define B_ 512
#define S_ 1024
#define T_ 64
#define FULLMASK 0xffffffffu

__device__ float g_ll[B_];
__device__ float g_len[B_];

typedef unsigned long long ull;

__device__ __forceinline__ ull ffma2(ull a, ull b, ull c) {
    ull d;
    asm("fma.rn.f32x2 %0, %1, %2, %3;" : "=l"(d) : "l"(a), "l"(b), "l"(c));
    return d;
}
__device__ __forceinline__ ull fadd2(ull a, ull b) {
    ull d;
    asm("add.rn.f32x2 %0, %1, %2;" : "=l"(d) : "l"(a), "l"(b));
    return d;
}
__device__ __forceinline__ ull pack2(float lo, float hi) {
    ull r;
    asm("mov.b64 %0, {%1, %2};" : "=l"(r) : "f"(lo), "f"(hi));
    return r;
}
__device__ __forceinline__ void unpack2(ull v, float& lo, float& hi) {
    asm("mov.b64 {%0, %1}, %2;" : "=f"(lo), "=f"(hi) : "l"(v));
}

// 8 warps/block = 4 batches/block (fwd+bwd warp per batch). grid = 128.
__global__ void __launch_bounds__(256) crf_main(
    const float* __restrict__ emis,
    const int* __restrict__ tags,
    const int* __restrict__ mask,
    const float* __restrict__ start,
    const float* __restrict__ endt,
    const float* __restrict__ trans)
{
    __shared__ __align__(16) float sh_w[8][2][T_];   // per-warp exchange, dbl-buffered
    __shared__ __align__(16) float sh_a[4][T_];      // forward's final alpha per pair
    __shared__ float sh_sc[4][2];                    // [pair][{csF, numF}]

    const int lane = threadIdx.x & 31;
    const int wid  = threadIdx.x >> 5;
    const int pair = wid >> 1;      // 0..3
    const int role = wid & 1;       // 0 = forward, 1 = backward
    const int b    = blockIdx.x * 4 + pair;

    const int j0 = 2 * lane;        // this lane's pair of states (cols fwd / rows bwd)
    const int j1 = j0 + 1;

    const int base = b * S_;
    const float* em = emis + (size_t)base * T_;
    const float2* ep = (const float2*)em;

    // ---- sequence length L (prefix mask); both warps compute it ----
    int lp = 0;
#pragma unroll 4
    for (int s = lane; s < S_; s += 32) lp += mask[base + s];
#pragma unroll
    for (int o = 16; o > 0; o >>= 1) lp += __shfl_xor_sync(FULLMASK, lp, o);
    const int L = lp;
    const int mid = L >> 1;

    if (role == 0) {
        // ================= FORWARD: alpha over s = 0..mid =================
        // E columns j0/j1: Ej0[m] = (exp(trans[2m][j0]), exp(trans[2m+1][j0]))
        ull Ej0[T_ / 2];
        ull Ej1[T_ / 2];
#pragma unroll
        for (int m = 0; m < T_ / 2; m++) {
            float2 ra = *(const float2*)&trans[(2 * m) * T_ + j0];
            float2 rb = *(const float2*)&trans[(2 * m + 1) * T_ + j0];
            Ej0[m] = pack2(__expf(ra.x), __expf(rb.x));
            Ej1[m] = pack2(__expf(ra.y), __expf(rb.y));
        }

        // numerator over s in [1, mid]
        float num = 0.0f;
        for (int s = 1 + lane; s <= mid; s += 32) {
            int tp = tags[base + s - 1];
            int tc = tags[base + s];
            num += trans[tp * T_ + tc] + em[s * T_ + tc];
        }
#pragma unroll
        for (int o = 16; o > 0; o >>= 1) num += __shfl_xor_sync(FULLMASK, num, o);
        if (lane == 0) {
            int tg0 = tags[base];
            num += start[tg0] + em[tg0];
        }

        // recursion init
        float2 e0 = ep[lane];
        float w0 = __expf(start[j0] + e0.x);
        float w1 = __expf(start[j1] + e0.y);

        float2 p1 = ep[1 * (T_ / 2) + lane];
        float2 p2 = ep[2 * (T_ / 2) + lane];
        float F0 = __expf(p1.x);
        float F1 = __expf(p1.y);
        p1 = p2;
        p2 = ep[3 * (T_ / 2) + lane];

        float r;
        int   kcur;
        {
            float w00 = __shfl_sync(FULLMASK, w0, 0);
            int k = ((__float_as_int(w00) >> 23) & 0xff) - 127;
            k = max(-126, min(126, k));
            r = __int_as_float((127 - k) << 23);
            kcur = k;
        }
        float csum = 0.0f;

        for (int s = 1; s <= mid; s++) {
            const int pb = s & 1;
            *(float2*)&sh_w[wid][pb][j0] = make_float2(w0, w1);
            __syncwarp();

            float Fn0 = __expf(p1.x);
            float Fn1 = __expf(p1.y);
            p1 = p2;
            int sp = s + 3; if (sp >= S_) sp = S_ - 1;
            p2 = ep[sp * (T_ / 2) + lane];

            const ulonglong2* q = (const ulonglong2*)sh_w[wid][pb];
            ull a00 = 0ull, a01 = 0ull, a02 = 0ull, a03 = 0ull;
            ull a10 = 0ull, a11 = 0ull, a12 = 0ull, a13 = 0ull;
#pragma unroll
            for (int m = 0; m < 8; m++) {
                ulonglong2 va = q[2 * m];
                ulonglong2 vb = q[2 * m + 1];
                a00 = ffma2(va.x, Ej0[4 * m + 0], a00);
                a01 = ffma2(va.y, Ej0[4 * m + 1], a01);
                a02 = ffma2(vb.x, Ej0[4 * m + 2], a02);
                a03 = ffma2(vb.y, Ej0[4 * m + 3], a03);
                a10 = ffma2(va.x, Ej1[4 * m + 0], a10);
                a11 = ffma2(va.y, Ej1[4 * m + 1], a11);
                a12 = ffma2(vb.x, Ej1[4 * m + 2], a12);
                a13 = ffma2(vb.y, Ej1[4 * m + 3], a13);
            }
            ull t0 = fadd2(fadd2(a00, a01), fadd2(a02, a03));
            ull t1 = fadd2(fadd2(a10, a11), fadd2(a12, a13));
            float s0l, s0h, s1l, s1h;
            unpack2(t0, s0l, s0h);
            unpack2(t1, s1l, s1h);

            w0 = (s0l + s0h) * (F0 * r);
            w1 = (s1l + s1h) * (F1 * r);
            csum += (float)kcur;

            float w00 = __shfl_sync(FULLMASK, w0, 0);
            int k = ((__float_as_int(w00) >> 23) & 0xff) - 127;
            k = max(-126, min(126, k));
            r = __int_as_float((127 - k) << 23);
            kcur = k;

            F0 = Fn0;
            F1 = Fn1;
        }

        // publish alpha_mid (scaled) + scalars
        *(float2*)&sh_a[pair][j0] = make_float2(w0, w1);
        if (lane == 0) {
            sh_sc[pair][0] = csum;
            sh_sc[pair][1] = num;
        }
    } else {
        // ================= BACKWARD: beta over s = L-1..mid =================
        // E rows i0/i1: Ri0[m] = (exp(trans[i0][2m]), exp(trans[i0][2m+1]))
        ull Ri0[T_ / 2];
        ull Ri1[T_ / 2];
#pragma unroll
        for (int m = 0; m < T_ / 2; m++) {
            float2 ra = *(const float2*)&trans[j0 * T_ + 2 * m];
            float2 rb = *(const float2*)&trans[j1 * T_ + 2 * m];
            Ri0[m] = pack2(__expf(ra.x), __expf(ra.y));
            Ri1[m] = pack2(__expf(rb.x), __expf(rb.y));
        }

        // numerator over s in (mid, L)
        float num = 0.0f;
        for (int s = mid + 1 + lane; s < L; s += 32) {
            int tp = tags[base + s - 1];
            int tc = tags[base + s];
            num += trans[tp * T_ + tc] + em[s * T_ + tc];
        }
#pragma unroll
        for (int o = 16; o > 0; o >>= 1) num += __shfl_xor_sync(FULLMASK, num, o);
        if (lane == 0) {
            int tgl = tags[base + L - 1];
            num += endt[tgl];
        }

        // recursion init: beta_{L-1}[i] = exp(end[i])
        float b0 = __expf(endt[j0]);
        float b1 = __expf(endt[j1]);

        // descending prefetch: F = exp(em[t+1]); p1 = em[t], p2 = em[t-1]
        float2 p0 = ep[(L - 1) * (T_ / 2) + lane];
        float2 p1 = ep[(L - 2) * (T_ / 2) + lane];
        float2 p2 = ep[(L - 3) * (T_ / 2) + lane];
        float F0 = __expf(p0.x);
        float F1 = __expf(p0.y);

        float r;
        int   kcur;
        {
            float b00 = __shfl_sync(FULLMASK, b0, 0);
            int k = ((__float_as_int(b00) >> 23) & 0xff) - 127;
            k = max(-126, min(126, k));
            r = __int_as_float((127 - k) << 23);
            kcur = k;
        }
        float csum = 0.0f;

        for (int t = L - 2; t >= mid; t--) {
            const int pb = t & 1;
            // u = F_{t+1} ∘ beta_{t+1}   (both off-chain-ready)
            *(float2*)&sh_w[wid][pb][j0] = make_float2(b0 * F0, b1 * F1);
            __syncwarp();

            float Fn0 = __expf(p1.x);
            float Fn1 = __expf(p1.y);
            p1 = p2;
            int tp2 = t - 2; if (tp2 < 0) tp2 = 0;
            p2 = ep[tp2 * (T_ / 2) + lane];

            // matvec: v[i] = sum_j E[i][j] * u[j]
            const ulonglong2* q = (const ulonglong2*)sh_w[wid][pb];
            ull a00 = 0ull, a01 = 0ull, a02 = 0ull, a03 = 0ull;
            ull a10 = 0ull, a11 = 0ull, a12 = 0ull, a13 = 0ull;
#pragma unroll
            for (int m = 0; m < 8; m++) {
                ulonglong2 va = q[2 * m];
                ulonglong2 vb = q[2 * m + 1];
                a00 = ffma2(va.x, Ri0[4 * m + 0], a00);
                a01 = ffma2(va.y, Ri0[4 * m + 1], a01);
                a02 = ffma2(vb.x, Ri0[4 * m + 2], a02);
                a03 = ffma2(vb.y, Ri0[4 * m + 3], a03);
                a10 = ffma2(va.x, Ri1[4 * m + 0], a10);
                a11 = ffma2(va.y, Ri1[4 * m + 1], a11);
                a12 = ffma2(vb.x, Ri1[4 * m + 2], a12);
                a13 = ffma2(vb.y, Ri1[4 * m + 3], a13);
            }
            ull t0 = fadd2(fadd2(a00, a01), fadd2(a02, a03));
            ull t1 = fadd2(fadd2(a10, a11), fadd2(a12, a13));
            float s0l, s0h, s1l, s1h;
            unpack2(t0, s0l, s0h);
            unpack2(t1, s1l, s1h);

            // apply pending rescale (r from previous sample, shadowed)
            b0 = (s0l + s0h) * r;
            b1 = (s1l + s1h) * r;
            csum += (float)kcur;

            float b00 = __shfl_sync(FULLMASK, b0, 0);
            int k = ((__float_as_int(b00) >> 23) & 0xff) - 127;
            k = max(-126, min(126, k));
            r = __int_as_float((127 - k) << 23);
            kcur = k;

            F0 = Fn0;
            F1 = Fn1;
        }

        // stash beta + scalars in regs; join after block sync below
        // (fall through)
        __syncthreads();

        // ---- join: Z = sum_i alpha_mid[i] * beta_mid[i] ----
        float2 a = *(const float2*)&sh_a[pair][j0];
        float e = a.x * b0 + a.y * b1;
#pragma unroll
        for (int o = 16; o > 0; o >>= 1) e += __shfl_xor_sync(FULLMASK, e, o);
        if (lane == 0) {
            float csF  = sh_sc[pair][0];
            float numF = sh_sc[pair][1];
            float den = (float)(((double)csF + (double)csum) * 0.6931471805599453)
                        + __logf(e);
            g_ll[b]  = (numF + num) - den;
            g_len[b] = (float)L;
        }
        return;
    }
    // forward warps arrive here
    __syncthreads();
}

__global__ void crf_finalize(float* __restrict__ out) {
    __shared__ float s_ll[16];
    __shared__ float s_ln[16];
    int t = threadIdx.x;  // 512 threads
    float ll = g_ll[t];
    float ln = g_len[t];
#pragma unroll
    for (int o = 16; o > 0; o >>= 1) {
        ll += __shfl_xor_sync(FULLMASK, ll, o);
        ln += __shfl_xor_sync(FULLMASK, ln, o);
    }
    int w = t >> 5;
    if ((t & 31) == 0) { s_ll[w] = ll; s_ln[w] = ln; }
    __syncthreads();
    if (t == 0) {
        float sll = 0.0f, sln = 0.0f;
#pragma unroll
        for (int i = 0; i < 16; i++) { sll += s_ll[i]; sln += s_ln[i]; }
        out[0] = -(sll / sln);
    }
}

extern "C" void kernel_launch(void* const* d_in, const int* in_sizes, int n_in,
                              void* d_out, int out_size) {
    const float* emis  = (const float*)d_in[0];
    const int*   tags  = (const int*)d_in[1];
    const int*   mask  = (const int*)d_in[2];
    const float* start = (const float*)d_in[3];
    const float* endt  = (const float*)d_in[4];
    const float* trans = (const float*)d_in[5];
    float* out = (float*)d_out;

    crf_main<<<B_ / 4, 256>>>(emis, tags, mask, start, endt, trans);
    crf_finalize<<<1, B_>>>(out);
}

// round 8
// speedup vs baseline: 3.2854x; 1.1107x over previous
#include <cuda_runtime.h>
#include <cuda_bf16.h>

// CRF NLL: B=512, S=1024, T=64.
// inputs: 0 emissions (B,S,T) f32, 1 tags (B,S) i32, 2 mask (B,S) i32,
//         3 start (T) f32, 4 end (T) f32, 5 transitions (T,T) f32
// output: scalar f32 = -(sum_b ll_b) / (sum_b L_b)
//
// Forward-backward split (Z = alpha_mid . beta_mid), scaled linear domain,
// with the T x T matvec done in packed bf16 (HFMA2, rt2, 2 MAC/instr).
// Scale bookkeeping, emissions exp, and rescale stay in f32 off-chain.
// Per-step log-Z noise ~4e-3 random-walks to ~7e-6 on the final mean —
// 100x under the 1e-3 threshold.

#define B_ 512
#define S_ 1024
#define T_ 64
#define FULLMASK 0xffffffffu

__device__ float g_ll[B_];
__device__ float g_len[B_];

typedef __nv_bfloat162 bf2;

__device__ __forceinline__ bf2 bf2pack(float lo, float hi) {
    return __float22bfloat162_rn(make_float2(lo, hi));
}

// 8 warps/block = 4 batches/block (fwd+bwd warp per batch). grid = 128.
__global__ void __launch_bounds__(256) crf_main(
    const float* __restrict__ emis,
    const int* __restrict__ tags,
    const int* __restrict__ mask,
    const float* __restrict__ start,
    const float* __restrict__ endt,
    const float* __restrict__ trans)
{
    __shared__ __align__(16) bf2 sh_w[8][2][32];     // per-warp exchange (bf16), dbl-buffered
    __shared__ __align__(16) float sh_a[4][T_];      // forward's final alpha per pair (f32)
    __shared__ float sh_sc[4][2];                    // [pair][{csF, numF}]

    const int lane = threadIdx.x & 31;
    const int wid  = threadIdx.x >> 5;
    const int pair = wid >> 1;      // 0..3
    const int role = wid & 1;       // 0 = forward, 1 = backward
    const int b    = blockIdx.x * 4 + pair;

    const int j0 = 2 * lane;        // this lane's pair of states (cols fwd / rows bwd)
    const int j1 = j0 + 1;

    const int base = b * S_;
    const float* em = emis + (size_t)base * T_;
    const float2* ep = (const float2*)em;

    // ---- sequence length L (prefix mask) ----
    int lp = 0;
#pragma unroll 4
    for (int s = lane; s < S_; s += 32) lp += mask[base + s];
#pragma unroll
    for (int o = 16; o > 0; o >>= 1) lp += __shfl_xor_sync(FULLMASK, lp, o);
    const int L = lp;
    const int mid = L >> 1;

    if (role == 0) {
        // ================= FORWARD: alpha over s = 0..mid =================
        // Ej0[m] = bf16(E[2m][j0], E[2m+1][j0]);  Ej1 likewise for column j1.
        bf2 Ej0[T_ / 2];
        bf2 Ej1[T_ / 2];
#pragma unroll
        for (int m = 0; m < T_ / 2; m++) {
            float2 ra = *(const float2*)&trans[(2 * m) * T_ + j0];
            float2 rb = *(const float2*)&trans[(2 * m + 1) * T_ + j0];
            Ej0[m] = bf2pack(__expf(ra.x), __expf(rb.x));
            Ej1[m] = bf2pack(__expf(ra.y), __expf(rb.y));
        }

        // numerator over s in [1, mid]
        float num = 0.0f;
        for (int s = 1 + lane; s <= mid; s += 32) {
            int tp = tags[base + s - 1];
            int tc = tags[base + s];
            num += trans[tp * T_ + tc] + em[s * T_ + tc];
        }
#pragma unroll
        for (int o = 16; o > 0; o >>= 1) num += __shfl_xor_sync(FULLMASK, num, o);
        if (lane == 0) {
            int tg0 = tags[base];
            num += start[tg0] + em[tg0];
        }

        // recursion init
        float2 e0 = ep[lane];
        float w0 = __expf(start[j0] + e0.x);
        float w1 = __expf(start[j1] + e0.y);

        float2 p1 = ep[1 * (T_ / 2) + lane];
        float2 p2 = ep[2 * (T_ / 2) + lane];
        float F0 = __expf(p1.x);
        float F1 = __expf(p1.y);
        p1 = p2;
        p2 = ep[3 * (T_ / 2) + lane];

        float r;
        int   kcur;
        {
            float w00 = __shfl_sync(FULLMASK, w0, 0);
            int k = ((__float_as_int(w00) >> 23) & 0xff) - 127;
            k = max(-126, min(126, k));
            r = __int_as_float((127 - k) << 23);
            kcur = k;
        }
        float csum = 0.0f;

        const bf2 z2 = bf2pack(0.0f, 0.0f);

        for (int s = 1; s <= mid; s++) {
            const int pb = s & 1;
            sh_w[wid][pb][lane] = bf2pack(w0, w1);
            __syncwarp();

            float Fn0 = __expf(p1.x);
            float Fn1 = __expf(p1.y);
            p1 = p2;
            int sp = s + 3; if (sp >= S_) sp = S_ - 1;
            p2 = ep[sp * (T_ / 2) + lane];

            // matvec: acc lanes hold i-parity split for one output column.
            const uint4* q = (const uint4*)sh_w[wid][pb];  // 8 x (4 bf2)
            bf2 a00 = z2, a01 = z2, a02 = z2, a03 = z2;    // output j0
            bf2 a10 = z2, a11 = z2, a12 = z2, a13 = z2;    // output j1
#pragma unroll
            for (int g = 0; g < 8; g++) {
                uint4 v = q[g];
                bf2 ws0 = *(bf2*)&v.x;   // (w[8g+0], w[8g+1])
                bf2 ws1 = *(bf2*)&v.y;
                bf2 ws2 = *(bf2*)&v.z;
                bf2 ws3 = *(bf2*)&v.w;
                a00 = __hfma2(ws0, Ej0[4 * g + 0], a00);
                a01 = __hfma2(ws1, Ej0[4 * g + 1], a01);
                a02 = __hfma2(ws2, Ej0[4 * g + 2], a02);
                a03 = __hfma2(ws3, Ej0[4 * g + 3], a03);
                a10 = __hfma2(ws0, Ej1[4 * g + 0], a10);
                a11 = __hfma2(ws1, Ej1[4 * g + 1], a11);
                a12 = __hfma2(ws2, Ej1[4 * g + 2], a12);
                a13 = __hfma2(ws3, Ej1[4 * g + 3], a13);
            }
            bf2 s0 = __hadd2(__hadd2(a00, a01), __hadd2(a02, a03));
            bf2 s1 = __hadd2(__hadd2(a10, a11), __hadd2(a12, a13));
            float2 f0 = __bfloat1622float2(s0);
            float2 f1 = __bfloat1622float2(s1);

            w0 = (f0.x + f0.y) * (F0 * r);
            w1 = (f1.x + f1.y) * (F1 * r);
            csum += (float)kcur;

            float w00 = __shfl_sync(FULLMASK, w0, 0);
            int k = ((__float_as_int(w00) >> 23) & 0xff) - 127;
            k = max(-126, min(126, k));
            r = __int_as_float((127 - k) << 23);
            kcur = k;

            F0 = Fn0;
            F1 = Fn1;
        }

        // publish alpha_mid (scaled, f32) + scalars
        *(float2*)&sh_a[pair][j0] = make_float2(w0, w1);
        if (lane == 0) {
            sh_sc[pair][0] = csum;
            sh_sc[pair][1] = num;
        }
    } else {
        // ================= BACKWARD: beta over s = L-1..mid =================
        // Ri0[m] = bf16(E[j0][2m], E[j0][2m+1]);  Ri1 likewise for row j1.
        bf2 Ri0[T_ / 2];
        bf2 Ri1[T_ / 2];
#pragma unroll
        for (int m = 0; m < T_ / 2; m++) {
            float2 ra = *(const float2*)&trans[j0 * T_ + 2 * m];
            float2 rb = *(const float2*)&trans[j1 * T_ + 2 * m];
            Ri0[m] = bf2pack(__expf(ra.x), __expf(ra.y));
            Ri1[m] = bf2pack(__expf(rb.x), __expf(rb.y));
        }

        // numerator over s in (mid, L)
        float num = 0.0f;
        for (int s = mid + 1 + lane; s < L; s += 32) {
            int tp = tags[base + s - 1];
            int tc = tags[base + s];
            num += trans[tp * T_ + tc] + em[s * T_ + tc];
        }
#pragma unroll
        for (int o = 16; o > 0; o >>= 1) num += __shfl_xor_sync(FULLMASK, num, o);
        if (lane == 0) {
            int tgl = tags[base + L - 1];
            num += endt[tgl];
        }

        // recursion init: beta_{L-1}[i] = exp(end[i])
        float b0 = __expf(endt[j0]);
        float b1 = __expf(endt[j1]);

        float2 p0 = ep[(L - 1) * (T_ / 2) + lane];
        float2 p1 = ep[(L - 2) * (T_ / 2) + lane];
        float2 p2 = ep[(L - 3) * (T_ / 2) + lane];
        float F0 = __expf(p0.x);
        float F1 = __expf(p0.y);

        float r;
        int   kcur;
        {
            float b00 = __shfl_sync(FULLMASK, b0, 0);
            int k = ((__float_as_int(b00) >> 23) & 0xff) - 127;
            k = max(-126, min(126, k));
            r = __int_as_float((127 - k) << 23);
            kcur = k;
        }
        float csum = 0.0f;

        const bf2 z2 = bf2pack(0.0f, 0.0f);

        for (int t = L - 2; t >= mid; t--) {
            const int pb = t & 1;
            // u = F_{t+1} o beta_{t+1}
            sh_w[wid][pb][lane] = bf2pack(b0 * F0, b1 * F1);
            __syncwarp();

            float Fn0 = __expf(p1.x);
            float Fn1 = __expf(p1.y);
            p1 = p2;
            int tp2 = t - 2; if (tp2 < 0) tp2 = 0;
            p2 = ep[tp2 * (T_ / 2) + lane];

            const uint4* q = (const uint4*)sh_w[wid][pb];
            bf2 a00 = z2, a01 = z2, a02 = z2, a03 = z2;    // output row j0
            bf2 a10 = z2, a11 = z2, a12 = z2, a13 = z2;    // output row j1
#pragma unroll
            for (int g = 0; g < 8; g++) {
                uint4 v = q[g];
                bf2 us0 = *(bf2*)&v.x;
                bf2 us1 = *(bf2*)&v.y;
                bf2 us2 = *(bf2*)&v.z;
                bf2 us3 = *(bf2*)&v.w;
                a00 = __hfma2(us0, Ri0[4 * g + 0], a00);
                a01 = __hfma2(us1, Ri0[4 * g + 1], a01);
                a02 = __hfma2(us2, Ri0[4 * g + 2], a02);
                a03 = __hfma2(us3, Ri0[4 * g + 3], a03);
                a10 = __hfma2(us0, Ri1[4 * g + 0], a10);
                a11 = __hfma2(us1, Ri1[4 * g + 1], a11);
                a12 = __hfma2(us2, Ri1[4 * g + 2], a12);
                a13 = __hfma2(us3, Ri1[4 * g + 3], a13);
            }
            bf2 s0 = __hadd2(__hadd2(a00, a01), __hadd2(a02, a03));
            bf2 s1 = __hadd2(__hadd2(a10, a11), __hadd2(a12, a13));
            float2 f0 = __bfloat1622float2(s0);
            float2 f1 = __bfloat1622float2(s1);

            b0 = (f0.x + f0.y) * r;
            b1 = (f1.x + f1.y) * r;
            csum += (float)kcur;

            float b00 = __shfl_sync(FULLMASK, b0, 0);
            int k = ((__float_as_int(b00) >> 23) & 0xff) - 127;
            k = max(-126, min(126, k));
            r = __int_as_float((127 - k) << 23);
            kcur = k;

            F0 = Fn0;
            F1 = Fn1;
        }

        __syncthreads();

        // ---- join: Z = sum_i alpha_mid[i] * beta_mid[i] ----
        float2 a = *(const float2*)&sh_a[pair][j0];
        float e = a.x * b0 + a.y * b1;
#pragma unroll
        for (int o = 16; o > 0; o >>= 1) e += __shfl_xor_sync(FULLMASK, e, o);
        if (lane == 0) {
            float csF  = sh_sc[pair][0];
            float numF = sh_sc[pair][1];
            float den = (float)(((double)csF + (double)csum) * 0.6931471805599453)
                        + __logf(e);
            g_ll[b]  = (numF + num) - den;
            g_len[b] = (float)L;
        }
        return;
    }
    // forward warps arrive here
    __syncthreads();
}

__global__ void crf_finalize(float* __restrict__ out) {
    __shared__ float s_ll[16];
    __shared__ float s_ln[16];
    int t = threadIdx.x;  // 512 threads
    float ll = g_ll[t];
    float ln = g_len[t];
#pragma unroll
    for (int o = 16; o > 0; o >>= 1) {
        ll += __shfl_xor_sync(FULLMASK, ll, o);
        ln += __shfl_xor_sync(FULLMASK, ln, o);
    }
    int w = t >> 5;
    if ((t & 31) == 0) { s_ll[w] = ll; s_ln[w] = ln; }
    __syncthreads();
    if (t == 0) {
        float sll = 0.0f, sln = 0.0f;
#pragma unroll
        for (int i = 0; i < 16; i++) { sll += s_ll[i]; sln += s_ln[i]; }
        out[0] = -(sll / sln);
    }
}

extern "C" void kernel_launch(void* const* d_in, const int* in_sizes, int n_in,
                              void* d_out, int out_size) {
    const float* emis  = (const float*)d_in[0];
    const int*   tags  = (const int*)d_in[1];
    const int*   mask  = (const int*)d_in[2];
    const float* start = (const float*)d_in[3];
    const float* endt  = (const float*)d_in[4];
    const float* trans = (const float*)d_in[5];
    float* out = (float*)d_out;

    crf_main<<<B_ / 4, 256>>>(emis, tags, mask, start, endt, trans);
    crf_finalize<<<1, B_>>>(out);
}